// round 3
// baseline (speedup 1.0000x reference)
#include <cuda_runtime.h>
#include <cuda_bf16.h>

// SparseAttention (entmax-1.5) fused kernel, GB300 sm_103a. Round 3:
//  - 512 threads / 16 warps (4x4 warp grid, 32x32 warp tiles): halves register
//    pressure (acc 32 vs 64 floats), doubles warps/SMSP for latency hiding.
//  - bf16 pre-convert prologue + 3-stage cp.async K pipeline (unchanged).
//  - candidate collect + exact fp32 rescore + 100-iter bisection (unchanged numerics).

#define BATCH 8
#define SEQ   2048
#define DIM   128
#define BM    128
#define BN    128
#define NT    (SEQ / BN)
#define QT    (SEQ / BM)
#define CAP   64
#define CSTR  65
#define QSTR  136              // bf16 row stride (128+8 pad): 16B aligned, ldsm conflict-free
#define NITER 100
#define STAGES 3
#define NTHREADS 512

#define TILE_B  (BM * QSTR * 2)                       // 34816 bytes per bf16 tile
#define OFF_QHI  0
#define OFF_KHI  (OFF_QHI + TILE_B)
#define OFF_CS   (OFF_KHI + STAGES * TILE_B)
#define OFF_CC   (OFF_CS + BM * CSTR * 4)
#define OFF_RM   (OFF_CC + BM * CSTR * 4)
#define OFF_CNT  (OFF_RM + BM * 4)
#define OFF_TAU  (OFF_CNT + BM * 4)
#define OFF_Z    (OFF_TAU + BM * 4)
#define SMEM_BYTES (OFF_Z + BM * 4)                   // 207872

__device__ __nv_bfloat16 g_Qh[BATCH * SEQ * DIM];
__device__ __nv_bfloat16 g_Kh[BATCH * SEQ * DIM];

__global__ void cvt_kernel(const float* __restrict__ Q, const float* __restrict__ K) {
    size_t i = ((size_t)blockIdx.x * blockDim.x + threadIdx.x) * 4;
    float4 q = *(const float4*)(Q + i);
    float4 k = *(const float4*)(K + i);
    __nv_bfloat162 q0, q1, k0, k1;
    q0.x = __float2bfloat16(q.x); q0.y = __float2bfloat16(q.y);
    q1.x = __float2bfloat16(q.z); q1.y = __float2bfloat16(q.w);
    k0.x = __float2bfloat16(k.x); k0.y = __float2bfloat16(k.y);
    k1.x = __float2bfloat16(k.z); k1.y = __float2bfloat16(k.w);
    *(__nv_bfloat162*)(g_Qh + i)     = q0;
    *(__nv_bfloat162*)(g_Qh + i + 2) = q1;
    *(__nv_bfloat162*)(g_Kh + i)     = k0;
    *(__nv_bfloat162*)(g_Kh + i + 2) = k1;
}

static __device__ __forceinline__ unsigned fenc(float f) {
    unsigned u = __float_as_uint(f);
    return (u & 0x80000000u) ? ~u : (u | 0x80000000u);
}
static __device__ __forceinline__ float fdec(unsigned e) {
    return (e & 0x80000000u) ? __uint_as_float(e & 0x7fffffffu)
                             : __uint_as_float(~e);
}
static __device__ __forceinline__ void cpasync16(unsigned dst, const void* src) {
    asm volatile("cp.async.cg.shared.global [%0], [%1], 16;\n" :: "r"(dst), "l"(src));
}
static __device__ __forceinline__ void cp_commit() {
    asm volatile("cp.async.commit_group;\n");
}
template <int N>
static __device__ __forceinline__ void cp_wait() {
    asm volatile("cp.async.wait_group %0;\n" :: "n"(N));
}
static __device__ __forceinline__ void ldsm4(unsigned* r, unsigned addr) {
    asm volatile("ldmatrix.sync.aligned.m8n8.x4.shared.b16 {%0,%1,%2,%3}, [%4];\n"
                 : "=r"(r[0]), "=r"(r[1]), "=r"(r[2]), "=r"(r[3])
                 : "r"(addr) : "memory");
}
static __device__ __forceinline__ void ldsm2(unsigned* r, unsigned addr) {
    asm volatile("ldmatrix.sync.aligned.m8n8.x2.shared.b16 {%0,%1}, [%2];\n"
                 : "=r"(r[0]), "=r"(r[1])
                 : "r"(addr) : "memory");
}
static __device__ __forceinline__ void mma16816(float* c, const unsigned* a, const unsigned* b) {
    asm volatile("mma.sync.aligned.m16n8k16.row.col.f32.bf16.bf16.f32 "
                 "{%0,%1,%2,%3}, {%4,%5,%6,%7}, {%8,%9}, {%0,%1,%2,%3};\n"
                 : "+f"(c[0]), "+f"(c[1]), "+f"(c[2]), "+f"(c[3])
                 : "r"(a[0]), "r"(a[1]), "r"(a[2]), "r"(a[3]),
                   "r"(b[0]), "r"(b[1]));
}

__global__ __launch_bounds__(NTHREADS, 1)
void entmax_attn_kernel(const float* __restrict__ Q, const float* __restrict__ K,
                        const float* __restrict__ V, float* __restrict__ O)
{
    extern __shared__ unsigned char smem[];
    float*    candS = (float*)(smem + OFF_CS);
    int*      candC = (int*)(smem + OFF_CC);
    unsigned* rowM  = (unsigned*)(smem + OFF_RM);
    int*      cnt   = (int*)(smem + OFF_CNT);
    float*    tauA  = (float*)(smem + OFF_TAU);
    float*    zA    = (float*)(smem + OFF_Z);

    const int tid  = threadIdx.x;
    const int lane = tid & 31;
    const int wid  = tid >> 5;
    const int b    = blockIdx.y;
    const int q0   = blockIdx.x * BM;

    const float* Qb = Q + ((size_t)b * SEQ + q0) * DIM;
    const float* Kb = K + (size_t)b * SEQ * DIM;
    const float* Vb = V + (size_t)b * SEQ * DIM;
    const __nv_bfloat16* Qhb = g_Qh + ((size_t)b * SEQ + q0) * DIM;
    const __nv_bfloat16* Khb = g_Kh + (size_t)b * SEQ * DIM;

    const unsigned smemB = (unsigned)__cvta_generic_to_shared(smem);
    const unsigned qS = smemB + OFF_QHI;

    // 4x4 warp grid, 32x32 warp tiles
    const int wm = wid & 3;          // 4 warps in M (32 rows each)
    const int wn = wid >> 2;         // 4 warps in N (32 cols each)
    const int g  = lane >> 2;
    const int t  = lane & 3;

    const int aRow = (lane & 7) + ((lane >> 3) & 1) * 8;  // ldsm x4 (A)
    const int aK   = ((lane >> 4) & 1) * 8;
    const int bRow = lane & 7;                            // ldsm x2 (B)
    const int bK   = ((lane >> 3) & 1) * 8;

    if (tid < BM) { rowM[tid] = 0u; cnt[tid] = 0; }

    // fill mapping: 2048 16B chunks per tile, 4 per thread
    const int frow0 = tid >> 4;        // 0..31
    const int fc16  = tid & 15;

    #pragma unroll
    for (int k = 0; k < 4; k++) {      // Q tile
        int r = frow0 + k * 32;
        cpasync16(qS + r * (QSTR * 2) + fc16 * 16, Qhb + r * DIM + fc16 * 8);
    }
    {                                   // K tile 0
        unsigned kD = smemB + OFF_KHI;
        #pragma unroll
        for (int k = 0; k < 4; k++) {
            int r = frow0 + k * 32;
            cpasync16(kD + r * (QSTR * 2) + fc16 * 16, Khb + r * DIM + fc16 * 8);
        }
    }
    cp_commit();
    {                                   // K tile 1
        const __nv_bfloat16* Kt = Khb + (size_t)BN * DIM;
        unsigned kD = smemB + OFF_KHI + TILE_B;
        #pragma unroll
        for (int k = 0; k < 4; k++) {
            int r = frow0 + k * 32;
            cpasync16(kD + r * (QSTR * 2) + fc16 * 16, Kt + r * DIM + fc16 * 8);
        }
    }
    cp_commit();

    for (int nt = 0; nt < NT; nt++) {
        if (nt + 2 < NT) {
            const __nv_bfloat16* Kt = Khb + (size_t)(nt + 2) * BN * DIM;
            unsigned kD = smemB + OFF_KHI + ((nt + 2) % STAGES) * TILE_B;
            #pragma unroll
            for (int k = 0; k < 4; k++) {
                int r = frow0 + k * 32;
                cpasync16(kD + r * (QSTR * 2) + fc16 * 16, Kt + r * DIM + fc16 * 8);
            }
            cp_commit();
        }
        if (nt < NT - 2)       cp_wait<2>();
        else if (nt == NT - 2) cp_wait<1>();
        else                   cp_wait<0>();
        __syncthreads();

        const unsigned kS = smemB + OFF_KHI + (nt % STAGES) * TILE_B;

        float acc[2][4][4];
        #pragma unroll
        for (int m = 0; m < 2; m++)
            #pragma unroll
            for (int n = 0; n < 4; n++)
                #pragma unroll
                for (int e = 0; e < 4; e++) acc[m][n][e] = 0.f;

        #pragma unroll
        for (int ks = 0; ks < 8; ks++) {
            unsigned a[2][4], bb[4][2];
            #pragma unroll
            for (int m = 0; m < 2; m++)
                ldsm4(a[m], qS + (unsigned)(((wm * 32 + m * 16 + aRow) * QSTR + ks * 16 + aK) * 2));
            #pragma unroll
            for (int n = 0; n < 4; n++)
                ldsm2(bb[n], kS + (unsigned)(((wn * 32 + n * 8 + bRow) * QSTR + ks * 16 + bK) * 2));
            #pragma unroll
            for (int m = 0; m < 2; m++)
                #pragma unroll
                for (int n = 0; n < 4; n++)
                    mma16816(acc[m][n], a[m], bb[n]);
        }

        // per-row running max (encoded atomicMax)
        #pragma unroll
        for (int m = 0; m < 2; m++) {
            #pragma unroll
            for (int h = 0; h < 2; h++) {
                float lm = -3.0e38f;
                #pragma unroll
                for (int n = 0; n < 4; n++)
                    lm = fmaxf(lm, fmaxf(acc[m][n][h * 2], acc[m][n][h * 2 + 1]));
                lm = fmaxf(lm, __shfl_xor_sync(0xffffffffu, lm, 1));
                lm = fmaxf(lm, __shfl_xor_sync(0xffffffffu, lm, 2));
                if ((lane & 3) == 0)
                    atomicMax(&rowM[wm * 32 + m * 16 + h * 8 + g], fenc(lm));
            }
        }
        __syncthreads();

        // collect candidates: score > running rowmax - 3.5
        #pragma unroll
        for (int m = 0; m < 2; m++) {
            #pragma unroll
            for (int h = 0; h < 2; h++) {
                const int r = wm * 32 + m * 16 + h * 8 + g;
                const float thr = fdec(rowM[r]) - 3.5f;
                #pragma unroll
                for (int n = 0; n < 4; n++) {
                    #pragma unroll
                    for (int e = 0; e < 2; e++) {
                        float s = acc[m][n][h * 2 + e];
                        if (s > thr) {
                            int p = atomicAdd(&cnt[r], 1);
                            if (p < CAP) {
                                candS[r * CSTR + p] = s;
                                candC[r * CSTR + p] = nt * BN + wn * 32 + n * 8 + t * 2 + e;
                            }
                        }
                    }
                }
            }
        }
        __syncthreads();   // stage-buffer reuse safety
    }

    // ---- sort + exact fp32 rescore + bisection (lane-per-row, warps 0-3) ----
    if (wid < 4) {
        const int r = wid * 32 + lane;
        int c_ = cnt[r]; if (c_ > CAP) c_ = CAP;
        float* cs = candS + r * CSTR;
        int*   cc = candC + r * CSTR;

        for (int i = 1; i < c_; i++) {
            float sv = cs[i]; int kv = cc[i]; int j = i - 1;
            while (j >= 0 && cc[j] > kv) { cc[j + 1] = cc[j]; cs[j + 1] = cs[j]; j--; }
            cc[j + 1] = kv; cs[j + 1] = sv;
        }

        const float* qp = Qb + r * DIM;
        float smax = -3.0e38f;
        for (int j = 0; j < c_; j++) {
            const float* kp = Kb + (size_t)cc[j] * DIM;
            float s0 = 0.f, s1 = 0.f, s2 = 0.f, s3 = 0.f;
            #pragma unroll
            for (int d = 0; d < DIM / 4; d++) {
                float4 qv = *(const float4*)(qp + d * 4);
                float4 kv = *(const float4*)(kp + d * 4);
                s0 = fmaf(qv.x, kv.x, s0);
                s1 = fmaf(qv.y, kv.y, s1);
                s2 = fmaf(qv.z, kv.z, s2);
                s3 = fmaf(qv.w, kv.w, s3);
            }
            float s = (s0 + s1) + (s2 + s3);
            cs[j] = s;
            smax = fmaxf(smax, s);
        }

        const float zmax = 0.5f * smax;
        float tmin = zmax - 1.0f;
        float tmax = zmax - 0.022097086912079608f;   // float32(2048^-0.5)
        float tau = 0.5f * (tmin + tmax), Zv = 0.f;
        for (int it = 0; it < NITER; it++) {
            tau = 0.5f * (tmin + tmax);
            Zv = 0.f;
            for (int j = 0; j < c_; j++) {
                float dz = fmaxf(0.5f * cs[j] - tau, 0.f);
                Zv += dz * dz;
            }
            if (Zv >= 1.0f) tmin = tau; else tmax = tau;
        }
        tauA[r] = tau;
        zA[r]   = Zv;
    }
    __syncthreads();

    // ---- sparse P@V: 16 warps x 8 rows, float4 coalesced V gather ----
    for (int rr = 0; rr < 8; rr++) {
        const int r = wid * 8 + rr;
        int c_ = cnt[r]; if (c_ > CAP) c_ = CAP;
        const float tau = tauA[r];
        const float Zv  = zA[r];
        float ax = 0.f, ay = 0.f, az = 0.f, aw = 0.f;
        for (int j = 0; j < c_; j++) {
            float dz = fmaxf(0.5f * candS[r * CSTR + j] - tau, 0.f);
            float w = (dz * dz) / Zv;
            const float4 v = *(const float4*)(Vb + (size_t)candC[r * CSTR + j] * DIM + lane * 4);
            ax = fmaf(w, v.x, ax);
            ay = fmaf(w, v.y, ay);
            az = fmaf(w, v.z, az);
            aw = fmaf(w, v.w, aw);
        }
        *(float4*)(O + ((size_t)b * SEQ + q0 + r) * DIM + lane * 4) = make_float4(ax, ay, az, aw);
    }
}

extern "C" void kernel_launch(void* const* d_in, const int* in_sizes, int n_in,
                              void* d_out, int out_size) {
    const float* Q = (const float*)d_in[0];
    const float* K = (const float*)d_in[1];
    const float* V = (const float*)d_in[2];
    float* O = (float*)d_out;

    cvt_kernel<<<2048, 256>>>(Q, K);

    cudaFuncSetAttribute(entmax_attn_kernel,
                         cudaFuncAttributeMaxDynamicSharedMemorySize, SMEM_BYTES);
    dim3 grid(QT, BATCH);
    entmax_attn_kernel<<<grid, NTHREADS, SMEM_BYTES>>>(Q, K, V, O);
}

// round 4
// speedup vs baseline: 1.4150x; 1.4150x over previous
#include <cuda_runtime.h>
#include <cuda_bf16.h>

// SparseAttention (entmax-1.5) fused kernel, GB300 sm_103a. Round 4:
//  - TAIL FIX: warp-per-row coalesced fp32 rescore (was lane-per-row with ~32
//    L1 wavefronts per LDG); thread-per-row bisection; all 16 warps used.
//  - mainloop: ldsm4 for B operands (2 instead of 4 ldsm2 per ks per warp).
//  - bf16 pre-convert prologue + 3-stage cp.async K pipeline unchanged.

#define BATCH 8
#define SEQ   2048
#define DIM   128
#define BM    128
#define BN    128
#define NT    (SEQ / BN)
#define QT    (SEQ / BM)
#define CAP   64
#define CSTR  65
#define QSTR  136              // bf16 row stride (128+8 pad): 16B aligned, ldsm conflict-free
#define NITER 100
#define STAGES 3
#define NTHREADS 512

#define TILE_B  (BM * QSTR * 2)                       // 34816 bytes per bf16 tile
#define OFF_QHI  0
#define OFF_KHI  (OFF_QHI + TILE_B)
#define OFF_CS   (OFF_KHI + STAGES * TILE_B)
#define OFF_CC   (OFF_CS + BM * CSTR * 4)
#define OFF_RM   (OFF_CC + BM * CSTR * 4)
#define OFF_CNT  (OFF_RM + BM * 4)
#define OFF_TAU  (OFF_CNT + BM * 4)
#define OFF_Z    (OFF_TAU + BM * 4)
#define SMEM_BYTES (OFF_Z + BM * 4)                   // 207872

__device__ __nv_bfloat16 g_Qh[BATCH * SEQ * DIM];
__device__ __nv_bfloat16 g_Kh[BATCH * SEQ * DIM];

__global__ void cvt_kernel(const float* __restrict__ Q, const float* __restrict__ K) {
    size_t i = ((size_t)blockIdx.x * blockDim.x + threadIdx.x) * 4;
    float4 q = *(const float4*)(Q + i);
    float4 k = *(const float4*)(K + i);
    __nv_bfloat162 q0, q1, k0, k1;
    q0.x = __float2bfloat16(q.x); q0.y = __float2bfloat16(q.y);
    q1.x = __float2bfloat16(q.z); q1.y = __float2bfloat16(q.w);
    k0.x = __float2bfloat16(k.x); k0.y = __float2bfloat16(k.y);
    k1.x = __float2bfloat16(k.z); k1.y = __float2bfloat16(k.w);
    *(__nv_bfloat162*)(g_Qh + i)     = q0;
    *(__nv_bfloat162*)(g_Qh + i + 2) = q1;
    *(__nv_bfloat162*)(g_Kh + i)     = k0;
    *(__nv_bfloat162*)(g_Kh + i + 2) = k1;
}

static __device__ __forceinline__ unsigned fenc(float f) {
    unsigned u = __float_as_uint(f);
    return (u & 0x80000000u) ? ~u : (u | 0x80000000u);
}
static __device__ __forceinline__ float fdec(unsigned e) {
    return (e & 0x80000000u) ? __uint_as_float(e & 0x7fffffffu)
                             : __uint_as_float(~e);
}
static __device__ __forceinline__ void cpasync16(unsigned dst, const void* src) {
    asm volatile("cp.async.cg.shared.global [%0], [%1], 16;\n" :: "r"(dst), "l"(src));
}
static __device__ __forceinline__ void cp_commit() {
    asm volatile("cp.async.commit_group;\n");
}
template <int N>
static __device__ __forceinline__ void cp_wait() {
    asm volatile("cp.async.wait_group %0;\n" :: "n"(N));
}
static __device__ __forceinline__ void ldsm4(unsigned* r, unsigned addr) {
    asm volatile("ldmatrix.sync.aligned.m8n8.x4.shared.b16 {%0,%1,%2,%3}, [%4];\n"
                 : "=r"(r[0]), "=r"(r[1]), "=r"(r[2]), "=r"(r[3])
                 : "r"(addr) : "memory");
}
static __device__ __forceinline__ void mma16816(float* c, const unsigned* a, const unsigned* b) {
    asm volatile("mma.sync.aligned.m16n8k16.row.col.f32.bf16.bf16.f32 "
                 "{%0,%1,%2,%3}, {%4,%5,%6,%7}, {%8,%9}, {%0,%1,%2,%3};\n"
                 : "+f"(c[0]), "+f"(c[1]), "+f"(c[2]), "+f"(c[3])
                 : "r"(a[0]), "r"(a[1]), "r"(a[2]), "r"(a[3]),
                   "r"(b[0]), "r"(b[1]));
}

__global__ __launch_bounds__(NTHREADS, 1)
void entmax_attn_kernel(const float* __restrict__ Q, const float* __restrict__ K,
                        const float* __restrict__ V, float* __restrict__ O)
{
    extern __shared__ unsigned char smem[];
    float*    candS = (float*)(smem + OFF_CS);
    int*      candC = (int*)(smem + OFF_CC);
    unsigned* rowM  = (unsigned*)(smem + OFF_RM);
    int*      cnt   = (int*)(smem + OFF_CNT);
    float*    tauA  = (float*)(smem + OFF_TAU);
    float*    zA    = (float*)(smem + OFF_Z);

    const int tid  = threadIdx.x;
    const int lane = tid & 31;
    const int wid  = tid >> 5;
    const int b    = blockIdx.y;
    const int q0   = blockIdx.x * BM;

    const float* Qb = Q + ((size_t)b * SEQ + q0) * DIM;
    const float* Kb = K + (size_t)b * SEQ * DIM;
    const float* Vb = V + (size_t)b * SEQ * DIM;
    const __nv_bfloat16* Qhb = g_Qh + ((size_t)b * SEQ + q0) * DIM;
    const __nv_bfloat16* Khb = g_Kh + (size_t)b * SEQ * DIM;

    const unsigned smemB = (unsigned)__cvta_generic_to_shared(smem);
    const unsigned qS = smemB + OFF_QHI;

    // 4x4 warp grid, 32x32 warp tiles
    const int wm = wid & 3;
    const int wn = wid >> 2;
    const int g  = lane >> 2;
    const int t  = lane & 3;

    const int aRow = (lane & 7) + ((lane >> 3) & 1) * 8;  // ldsm x4 (A)
    const int aK   = ((lane >> 4) & 1) * 8;
    // ldsm x4 (B): 4 matrices = 2 n-blocks x 2 k-halves
    const int bGrp  = lane >> 3;
    const int bRow4 = ((bGrp >> 1) & 1) * 8 + (lane & 7);
    const int bK4   = (bGrp & 1) * 8;

    if (tid < BM) { rowM[tid] = 0u; cnt[tid] = 0; }

    const int frow0 = tid >> 4;
    const int fc16  = tid & 15;

    #pragma unroll
    for (int k = 0; k < 4; k++) {      // Q tile
        int r = frow0 + k * 32;
        cpasync16(qS + r * (QSTR * 2) + fc16 * 16, Qhb + r * DIM + fc16 * 8);
    }
    {                                   // K tile 0
        unsigned kD = smemB + OFF_KHI;
        #pragma unroll
        for (int k = 0; k < 4; k++) {
            int r = frow0 + k * 32;
            cpasync16(kD + r * (QSTR * 2) + fc16 * 16, Khb + r * DIM + fc16 * 8);
        }
    }
    cp_commit();
    {                                   // K tile 1
        const __nv_bfloat16* Kt = Khb + (size_t)BN * DIM;
        unsigned kD = smemB + OFF_KHI + TILE_B;
        #pragma unroll
        for (int k = 0; k < 4; k++) {
            int r = frow0 + k * 32;
            cpasync16(kD + r * (QSTR * 2) + fc16 * 16, Kt + r * DIM + fc16 * 8);
        }
    }
    cp_commit();

    for (int nt = 0; nt < NT; nt++) {
        if (nt + 2 < NT) {
            const __nv_bfloat16* Kt = Khb + (size_t)(nt + 2) * BN * DIM;
            unsigned kD = smemB + OFF_KHI + ((nt + 2) % STAGES) * TILE_B;
            #pragma unroll
            for (int k = 0; k < 4; k++) {
                int r = frow0 + k * 32;
                cpasync16(kD + r * (QSTR * 2) + fc16 * 16, Kt + r * DIM + fc16 * 8);
            }
            cp_commit();
        }
        if (nt < NT - 2)       cp_wait<2>();
        else if (nt == NT - 2) cp_wait<1>();
        else                   cp_wait<0>();
        __syncthreads();

        const unsigned kS = smemB + OFF_KHI + (nt % STAGES) * TILE_B;

        float acc[2][4][4];
        #pragma unroll
        for (int m = 0; m < 2; m++)
            #pragma unroll
            for (int n = 0; n < 4; n++)
                #pragma unroll
                for (int e = 0; e < 4; e++) acc[m][n][e] = 0.f;

        #pragma unroll
        for (int ks = 0; ks < 8; ks++) {
            unsigned a[2][4], bb[2][4];
            #pragma unroll
            for (int m = 0; m < 2; m++)
                ldsm4(a[m], qS + (unsigned)(((wm * 32 + m * 16 + aRow) * QSTR + ks * 16 + aK) * 2));
            #pragma unroll
            for (int p = 0; p < 2; p++)
                ldsm4(bb[p], kS + (unsigned)(((wn * 32 + p * 16 + bRow4) * QSTR + ks * 16 + bK4) * 2));
            #pragma unroll
            for (int m = 0; m < 2; m++)
                #pragma unroll
                for (int p = 0; p < 2; p++) {
                    mma16816(acc[m][p * 2],     a[m], &bb[p][0]);
                    mma16816(acc[m][p * 2 + 1], a[m], &bb[p][2]);
                }
        }

        // per-row running max (encoded atomicMax)
        #pragma unroll
        for (int m = 0; m < 2; m++) {
            #pragma unroll
            for (int h = 0; h < 2; h++) {
                float lm = -3.0e38f;
                #pragma unroll
                for (int n = 0; n < 4; n++)
                    lm = fmaxf(lm, fmaxf(acc[m][n][h * 2], acc[m][n][h * 2 + 1]));
                lm = fmaxf(lm, __shfl_xor_sync(0xffffffffu, lm, 1));
                lm = fmaxf(lm, __shfl_xor_sync(0xffffffffu, lm, 2));
                if ((lane & 3) == 0)
                    atomicMax(&rowM[wm * 32 + m * 16 + h * 8 + g], fenc(lm));
            }
        }
        __syncthreads();

        // collect candidates: score > running rowmax - 3.5
        #pragma unroll
        for (int m = 0; m < 2; m++) {
            #pragma unroll
            for (int h = 0; h < 2; h++) {
                const int r = wm * 32 + m * 16 + h * 8 + g;
                const float thr = fdec(rowM[r]) - 3.5f;
                #pragma unroll
                for (int n = 0; n < 4; n++) {
                    #pragma unroll
                    for (int e = 0; e < 2; e++) {
                        float s = acc[m][n][h * 2 + e];
                        if (s > thr) {
                            int p = atomicAdd(&cnt[r], 1);
                            if (p < CAP) {
                                candS[r * CSTR + p] = s;
                                candC[r * CSTR + p] = nt * BN + wn * 32 + n * 8 + t * 2 + e;
                            }
                        }
                    }
                }
            }
        }
        __syncthreads();   // stage-buffer reuse safety
    }
    __syncthreads();

    // ---- deterministic order: per-row insertion sort by column (threads 0-127) ----
    if (tid < BM) {
        const int r = tid;
        int c_ = cnt[r]; if (c_ > CAP) { c_ = CAP; cnt[r] = CAP; }
        float* cs = candS + r * CSTR;
        int*   cc = candC + r * CSTR;
        for (int i = 1; i < c_; i++) {
            float sv = cs[i]; int kv = cc[i]; int j = i - 1;
            while (j >= 0 && cc[j] > kv) { cc[j + 1] = cc[j]; cs[j + 1] = cs[j]; j--; }
            cc[j + 1] = kv; cs[j + 1] = sv;
        }
    }
    __syncthreads();

    // ---- exact fp32 rescore: warp-per-row, coalesced K row loads ----
    for (int r = wid; r < BM; r += 16) {
        const int c_ = cnt[r];
        float* cs = candS + r * CSTR;
        int*   cc = candC + r * CSTR;
        const float4 qv = *(const float4*)(Qb + (size_t)r * DIM + lane * 4);
        for (int j = 0; j < c_; j++) {
            const float4 kv = *(const float4*)(Kb + (size_t)cc[j] * DIM + lane * 4);
            float d = fmaf(qv.x, kv.x, 0.f);
            d = fmaf(qv.y, kv.y, d);
            d = fmaf(qv.z, kv.z, d);
            d = fmaf(qv.w, kv.w, d);
            #pragma unroll
            for (int s = 16; s > 0; s >>= 1)
                d += __shfl_xor_sync(0xffffffffu, d, s);
            if (lane == 0) cs[j] = d;
        }
    }
    __syncthreads();

    // ---- bisection: thread-per-row (threads 0-127) ----
    if (tid < BM) {
        const int r = tid;
        const int c_ = cnt[r];
        float* cs = candS + r * CSTR;

        float smax = -3.0e38f;
        for (int j = 0; j < c_; j++) smax = fmaxf(smax, cs[j]);

        const float zmax = 0.5f * smax;
        float tmin = zmax - 1.0f;
        float tmax = zmax - 0.022097086912079608f;   // float32(2048^-0.5)
        float tau = 0.5f * (tmin + tmax), Zv = 0.f;
        for (int it = 0; it < NITER; it++) {
            tau = 0.5f * (tmin + tmax);
            Zv = 0.f;
            for (int j = 0; j < c_; j++) {
                float dz = fmaxf(0.5f * cs[j] - tau, 0.f);
                Zv += dz * dz;
            }
            if (Zv >= 1.0f) tmin = tau; else tmax = tau;
        }
        tauA[r] = tau;
        zA[r]   = Zv;
    }
    __syncthreads();

    // ---- sparse P@V: 16 warps x 8 rows, float4 coalesced V gather ----
    for (int rr = 0; rr < 8; rr++) {
        const int r = wid * 8 + rr;
        const int c_ = cnt[r];
        const float tau = tauA[r];
        const float Zv  = zA[r];
        float ax = 0.f, ay = 0.f, az = 0.f, aw = 0.f;
        for (int j = 0; j < c_; j++) {
            float dz = fmaxf(0.5f * candS[r * CSTR + j] - tau, 0.f);
            float w = (dz * dz) / Zv;
            const float4 v = *(const float4*)(Vb + (size_t)candC[r * CSTR + j] * DIM + lane * 4);
            ax = fmaf(w, v.x, ax);
            ay = fmaf(w, v.y, ay);
            az = fmaf(w, v.z, az);
            aw = fmaf(w, v.w, aw);
        }
        *(float4*)(O + ((size_t)b * SEQ + q0 + r) * DIM + lane * 4) = make_float4(ax, ay, az, aw);
    }
}

extern "C" void kernel_launch(void* const* d_in, const int* in_sizes, int n_in,
                              void* d_out, int out_size) {
    const float* Q = (const float*)d_in[0];
    const float* K = (const float*)d_in[1];
    const float* V = (const float*)d_in[2];
    float* O = (float*)d_out;

    cvt_kernel<<<2048, 256>>>(Q, K);

    cudaFuncSetAttribute(entmax_attn_kernel,
                         cudaFuncAttributeMaxDynamicSharedMemorySize, SMEM_BYTES);
    dim3 grid(QT, BATCH);
    entmax_attn_kernel<<<grid, NTHREADS, SMEM_BYTES>>>(Q, K, V, O);
}